// round 1
// baseline (speedup 1.0000x reference)
#include <cuda_runtime.h>
#include <cuda_bf16.h>

// out[k][d] = mult_k * sum_i W_k[eb_input[i]][d]   (offsets are mathematically dead)
// Strategy: histogram counts -> streaming weighted reduction over the tables.

#define MAX_EMB 2000000

// 8MB count scratch (zero-initialized at module load; each run re-zeroes it).
__device__ unsigned int g_count[MAX_EMB];
// 9 double accumulators, padded to 512B stride so atomics land on different L2 slices.
__device__ double g_acc[9 * 64];

// ---------------------------------------------------------------------------
// Kernel 1: histogram of indices.  2x int4 per thread, RED.ADD (no return).
// ---------------------------------------------------------------------------
__global__ void k_hist(const int* __restrict__ idx, int n_idx) {
    int t = blockIdx.x * blockDim.x + threadIdx.x;
    int n4 = n_idx >> 2;
    const int4* v = (const int4*)idx;
    int i = t * 2;
    if (i < n4) {
        int4 a = __ldg(v + i);
        atomicAdd(&g_count[a.x], 1u);
        atomicAdd(&g_count[a.y], 1u);
        atomicAdd(&g_count[a.z], 1u);
        atomicAdd(&g_count[a.w], 1u);
        if (i + 1 < n4) {
            int4 b = __ldg(v + i + 1);
            atomicAdd(&g_count[b.x], 1u);
            atomicAdd(&g_count[b.y], 1u);
            atomicAdd(&g_count[b.z], 1u);
            atomicAdd(&g_count[b.w], 1u);
        }
    }
    // scalar tail (n_idx not multiple of 4)
    if (blockIdx.x == 0) {
        int rem = n_idx & 3;
        if ((int)threadIdx.x < rem)
            atomicAdd(&g_count[idx[(n4 << 2) + threadIdx.x]], 1u);
    }
}

// ---------------------------------------------------------------------------
// Kernel 2: streaming sweep.  Each thread handles 4 rows (= 3 float4 per table),
// reads counts, zeroes them for the next graph replay, accumulates c*W.
// Block = 256 threads (8 warps).  Warp shuffle + shared reduce, then one
// double atomicAdd per block per output element.
// ---------------------------------------------------------------------------
__global__ void k_sweep(const float* __restrict__ W0,
                        const float* __restrict__ W1,
                        const float* __restrict__ W2,
                        int num_emb) {
    int t = blockIdx.x * blockDim.x + threadIdx.x;
    int r0 = t * 4;

    float acc[9];
#pragma unroll
    for (int k = 0; k < 9; k++) acc[k] = 0.0f;

    if (r0 + 4 <= num_emb) {
        uint4 c4 = *(const uint4*)&g_count[r0];
        *(uint4*)&g_count[r0] = make_uint4(0u, 0u, 0u, 0u);   // re-init for next replay
        float c0 = (float)c4.x, c1 = (float)c4.y, c2 = (float)c4.z, c3 = (float)c4.w;

        const float* Ws[3] = {W0, W1, W2};
#pragma unroll
        for (int k = 0; k < 3; k++) {
            const float4* Wv = (const float4*)Ws[k] + 3 * t;  // 12 floats = 4 rows
            float4 a = __ldg(Wv + 0);
            float4 b = __ldg(Wv + 1);
            float4 d = __ldg(Wv + 2);
            // rows:  r0: a.x a.y a.z | r0+1: a.w b.x b.y | r0+2: b.z b.w d.x | r0+3: d.y d.z d.w
            acc[3 * k + 0] += c0 * a.x + c1 * a.w + c2 * b.z + c3 * d.y;
            acc[3 * k + 1] += c0 * a.y + c1 * b.x + c2 * b.w + c3 * d.z;
            acc[3 * k + 2] += c0 * a.z + c1 * b.y + c2 * d.x + c3 * d.w;
        }
    } else if (r0 < num_emb) {
        // scalar tail rows
        for (int r = r0; r < num_emb; r++) {
            float c = (float)g_count[r];
            g_count[r] = 0u;
            const float* Ws[3] = {W0, W1, W2};
#pragma unroll
            for (int k = 0; k < 3; k++) {
                acc[3 * k + 0] += c * Ws[k][3 * r + 0];
                acc[3 * k + 1] += c * Ws[k][3 * r + 1];
                acc[3 * k + 2] += c * Ws[k][3 * r + 2];
            }
        }
    }

    // warp reduction (fp32: each warp covers only 128 rows, precision fine)
    unsigned lane = threadIdx.x & 31u;
    unsigned warp = threadIdx.x >> 5;
#pragma unroll
    for (int k = 0; k < 9; k++) {
#pragma unroll
        for (int o = 16; o > 0; o >>= 1)
            acc[k] += __shfl_down_sync(0xffffffffu, acc[k], o);
    }

    __shared__ float s_red[8][9];
    if (lane == 0) {
#pragma unroll
        for (int k = 0; k < 9; k++) s_red[warp][k] = acc[k];
    }
    __syncthreads();

    if (threadIdx.x < 9) {
        double s = 0.0;
#pragma unroll
        for (int w = 0; w < 8; w++) s += (double)s_red[w][threadIdx.x];
        atomicAdd(&g_acc[threadIdx.x * 64], s);
    }
}

// ---------------------------------------------------------------------------
// Kernel 3: scale, write output, re-zero accumulators for next replay.
// ---------------------------------------------------------------------------
__global__ void k_final(float* __restrict__ out) {
    int i = threadIdx.x;
    if (i < 9) {
        const float mult[3] = {5.0f, 10.0f, 6.0f};
        double v = g_acc[i * 64];
        g_acc[i * 64] = 0.0;
        out[i] = (float)((double)mult[i / 3] * v);
    }
}

// ---------------------------------------------------------------------------
extern "C" void kernel_launch(void* const* d_in, const int* in_sizes, int n_in,
                              void* d_out, int out_size) {
    const int*   idx = (const int*)d_in[0];
    // d_in[1] = eb_offset : mathematically unused (all bags summed at the end)
    const float* W0  = (const float*)d_in[2];
    const float* W1  = (const float*)d_in[3];
    const float* W2  = (const float*)d_in[4];
    int n_idx   = in_sizes[0];
    int num_emb = in_sizes[2] / 3;

    // histogram: each thread consumes 2 int4 = 8 indices
    int n4 = n_idx >> 2;
    int hist_threads = (n4 + 1) >> 1;
    int hist_blocks = (hist_threads + 255) / 256;
    if (hist_blocks < 1) hist_blocks = 1;
    k_hist<<<hist_blocks, 256>>>(idx, n_idx);

    // sweep: 4 rows per thread
    int sweep_threads = (num_emb + 3) / 4;
    int sweep_blocks = (sweep_threads + 255) / 256;
    if (sweep_blocks < 1) sweep_blocks = 1;
    k_sweep<<<sweep_blocks, 256>>>(W0, W1, W2, num_emb);

    k_final<<<1, 32>>>((float*)d_out);
}